// round 8
// baseline (speedup 1.0000x reference)
#include <cuda_runtime.h>
#include <math.h>
#include <stdint.h>

#define BATCH   4
#define S_LEN   2048
#define D_MODEL 1024
#define NHEADS  16
#define KD      64
#define M_ROWS  (BATCH * S_LEN)   // 8192
#define P_DIM   (NHEADS * KD)     // 1024
#define LOG2E   1.4426950408889634f

// ---------------------------------------------------------------------------
// Scratch (allocation-free rule: static __device__ globals)
// ---------------------------------------------------------------------------
__device__ float g_q[(size_t)M_ROWS * P_DIM];      // [B,H,S,Kd]
__device__ float g_k[(size_t)M_ROWS * P_DIM];      // [B,H,S,Kd]
__device__ float g_v[(size_t)M_ROWS * P_DIM];      // [B,H,S,Kd]
__device__ float g_attn[(size_t)M_ROWS * P_DIM];   // [B*S, H*Kd]
__device__ float g_wt[4][(size_t)D_MODEL * P_DIM]; // transposed+tf32 weights

// ---------------------------------------------------------------------------
// Base-ISA helpers (sm_103 WITHOUT 'a' — no tcgen05 anywhere)
// ---------------------------------------------------------------------------
__device__ __forceinline__ uint32_t round_tf32(float x) {
    uint32_t r;
    asm("cvt.rna.tf32.f32 %0, %1;" : "=r"(r) : "f"(x));
    return r;
}

// mma.sync m16n8k8 tf32 (sm_80+ base ISA)
#define MMA_TF32(d, a, b)                                                     \
    asm volatile(                                                             \
        "mma.sync.aligned.m16n8k8.row.col.f32.tf32.tf32.f32 "                 \
        "{%0,%1,%2,%3}, {%4,%5,%6,%7}, {%8,%9}, {%0,%1,%2,%3};"               \
        : "+f"((d)[0]), "+f"((d)[1]), "+f"((d)[2]), "+f"((d)[3])              \
        : "r"((a)[0]), "r"((a)[1]), "r"((a)[2]), "r"((a)[3]),                 \
          "r"((b)[0]), "r"((b)[1]))

// ---------------------------------------------------------------------------
// Weight transpose + tf32 round: WT[n][k] = round_tf32(W[k][n]), 1024x1024
// ---------------------------------------------------------------------------
__global__ __launch_bounds__(256)
void transpose_round(const float* __restrict__ W, float* __restrict__ WT)
{
    __shared__ float t[32][33];
    const int bx = blockIdx.x * 32, by = blockIdx.y * 32;
    const int x = threadIdx.x, y = threadIdx.y;
    #pragma unroll
    for (int i = 0; i < 32; i += 8)
        t[y + i][x] = W[(size_t)(by + y + i) * 1024 + bx + x];
    __syncthreads();
    #pragma unroll
    for (int i = 0; i < 32; i += 8)
        WT[(size_t)(bx + y + i) * 1024 + by + x] =
            __uint_as_float(round_tf32(t[x][y + i]));
}

// ---------------------------------------------------------------------------
// HMMA tf32 GEMM (validated in R6/R7): C = A[8192,1024]*BT^T + bias.
// ---------------------------------------------------------------------------
#define GBK 16
#define GNS (D_MODEL / GBK)   // 64 stages

template <int OUT_MODE>
__global__ __launch_bounds__(128)
void gemm_tf32(const float* __restrict__ A, const float* __restrict__ BT,
               const float* __restrict__ bias, float* __restrict__ C)
{
    __shared__ float sm[2 * 4096];   // 32 KB

    const int tid  = threadIdx.x;
    const int lane = tid & 31;
    const int wid  = tid >> 5;
    const int wm   = (wid >> 1) * 64;
    const int wn   = (wid & 1) * 64;
    const int rowBase = blockIdx.y * 128;
    const int colBase = blockIdx.x * 128;

    float acc[4][8][4];
    #pragma unroll
    for (int mf = 0; mf < 4; mf++)
        #pragma unroll
        for (int nf = 0; nf < 8; nf++)
            #pragma unroll
            for (int r = 0; r < 4; r++) acc[mf][nf][r] = 0.0f;

    uint4  stA[4];
    float4 stB[4];

    #pragma unroll
    for (int i = 0; i < 4; i++) {
        int idx = i * 128 + tid;
        int r = idx >> 2, c4 = idx & 3;
        float4 va = *(const float4*)(A + (size_t)(rowBase + r) * D_MODEL + c4 * 4);
        stA[i] = make_uint4(round_tf32(va.x), round_tf32(va.y),
                            round_tf32(va.z), round_tf32(va.w));
        stB[i] = *(const float4*)(BT + (size_t)(colBase + r) * D_MODEL + c4 * 4);
    }

    for (int s = 0; s < GNS; s++) {
        float* base = sm + (s & 1) * 4096;

        #pragma unroll
        for (int i = 0; i < 4; i++) {
            int idx = i * 128 + tid;
            int r = idx >> 2, c4 = idx & 3;
            int ks = c4 >> 1, kh = c4 & 1;
            int sw = ks + 4 * kh;
            {
                int mf = r >> 4, rr = r & 15;
                int half = rr >> 3, r8 = rr & 7;
                int reg = half + 2 * kh;
                *(uint4*)(base + (((mf * 2 + ks) * 4 + reg) * 32) +
                          ((r8 ^ sw) * 4)) = stA[i];
            }
            {
                int nf = r >> 3, c = r & 7;
                int reg = kh;
                *(float4*)(base + 2048 + (((nf * 2 + ks) * 2 + reg) * 32) +
                           ((c ^ sw) * 4)) = stB[i];
            }
        }
        __syncthreads();

        if (s + 1 < GNS) {
            int k0 = (s + 1) * GBK;
            #pragma unroll
            for (int i = 0; i < 4; i++) {
                int idx = i * 128 + tid;
                int r = idx >> 2, c4 = idx & 3;
                float4 va = *(const float4*)(A + (size_t)(rowBase + r) * D_MODEL +
                                             k0 + c4 * 4);
                stA[i] = make_uint4(round_tf32(va.x), round_tf32(va.y),
                                    round_tf32(va.z), round_tf32(va.w));
                stB[i] = *(const float4*)(BT + (size_t)(colBase + r) * D_MODEL +
                                          k0 + c4 * 4);
            }
        }

        #pragma unroll
        for (int ks = 0; ks < 2; ks++) {
            uint32_t a[4][4];
            uint32_t b[8][2];
            #pragma unroll
            for (int mf = 0; mf < 4; mf++) {
                int gmf = (wm >> 4) + mf;
                #pragma unroll
                for (int r = 0; r < 4; r++) {
                    int sw = ks + 4 * (r >> 1);
                    a[mf][r] = __float_as_uint(
                        base[(((gmf * 2 + ks) * 4 + r) * 32) + (lane ^ (4 * sw))]);
                }
            }
            #pragma unroll
            for (int nf = 0; nf < 8; nf++) {
                int gnf = (wn >> 3) + nf;
                #pragma unroll
                for (int r = 0; r < 2; r++) {
                    int sw = ks + 4 * r;
                    b[nf][r] = __float_as_uint(
                        base[2048 + (((gnf * 2 + ks) * 2 + r) * 32) +
                             (lane ^ (4 * sw))]);
                }
            }
            #pragma unroll
            for (int mf = 0; mf < 4; mf++)
                #pragma unroll
                for (int nf = 0; nf < 8; nf++)
                    MMA_TF32(acc[mf][nf], a[mf], b[nf]);
        }
        __syncthreads();
    }

    #pragma unroll
    for (int nf = 0; nf < 8; nf++) {
        int col = colBase + wn + nf * 8 + 2 * (lane & 3);
        float b0 = bias[col], b1 = bias[col + 1];
        #pragma unroll
        for (int mf = 0; mf < 4; mf++) {
            int row0 = rowBase + wm + mf * 16 + (lane >> 2);
            #pragma unroll
            for (int half = 0; half < 2; half++) {
                int row = row0 + half * 8;
                float v0 = acc[mf][nf][2 * half]     + b0;
                float v1 = acc[mf][nf][2 * half + 1] + b1;
                float* dst;
                if (OUT_MODE == 0) {
                    dst = C + (size_t)row * D_MODEL + col;
                } else {
                    int bb = row >> 11, srow = row & 2047;
                    int h = col >> 6, d0 = col & 63;
                    dst = C + (((size_t)(bb * NHEADS + h) * S_LEN + srow) * KD + d0);
                }
                *(float2*)dst = make_float2(v0, v1);
            }
        }
    }
}

// ---------------------------------------------------------------------------
// Tensor-core flash attention (tf32 HMMA), causal + ALiBi.
// Grid (S/64, B*H): blockIdx.x = q-block (reversed, heavy first),
// blockIdx.y = bh  -> co-resident CTAs share one head's K/V in L2.
// P accumulator->A-operand reshaping done with intra-quad shfl (no smem).
// Softmax in exp2 domain (log2e folded into Q scale and alibi slope).
// ---------------------------------------------------------------------------
#define FPAD 72
#define FA_SMEM (2 * 64 * FPAD * 4)   // Ks + Vs = 36864 bytes (< 48KB default)

__global__ __launch_bounds__(128)
void flash_alibi_tc(const float* __restrict__ Q, const float* __restrict__ K,
                    const float* __restrict__ V, float* __restrict__ O)
{
    extern __shared__ float fsm[];
    float* Ks = fsm;                    // [64][FPAD] tf32 bits
    float* Vs = fsm + 64 * FPAD;        // [64][FPAD] tf32 bits

    const int bh = blockIdx.y;
    const int h  = bh & (NHEADS - 1);
    const int b  = bh >> 4;
    const int qb = (int)gridDim.x - 1 - (int)blockIdx.x;  // heavy blocks first
    const int q0 = qb << 6;
    const int tid = threadIdx.x;
    const int lane = tid & 31;
    const int wid  = tid >> 5;
    const int g = lane >> 2;     // group id (row within 8)
    const int t = lane & 3;      // thread in group

    const float slope2 = exp2f(-0.5f * (float)(h + 1)) * LOG2E;
    const int r0 = q0 + wid * 16 + g;           // my fragment rows: r0, r0+8
    const float* Qb = Q + (size_t)bh * S_LEN * KD;
    const float* Kb = K + (size_t)bh * S_LEN * KD;
    const float* Vb = V + (size_t)bh * S_LEN * KD;

    // ---- Q fragments (resident), scaled by 0.125*log2e, tf32 ----
    const float qscale = 0.125f * LOG2E;
    uint32_t qa[8][4];
    #pragma unroll
    for (int kk = 0; kk < 8; kk++) {
        int d = kk * 8 + t;
        qa[kk][0] = round_tf32(Qb[(size_t)r0 * KD + d] * qscale);
        qa[kk][1] = round_tf32(Qb[(size_t)(r0 + 8) * KD + d] * qscale);
        qa[kk][2] = round_tf32(Qb[(size_t)r0 * KD + d + 4] * qscale);
        qa[kk][3] = round_tf32(Qb[(size_t)(r0 + 8) * KD + d + 4] * qscale);
    }

    float oacc[8][4];
    #pragma unroll
    for (int nf = 0; nf < 8; nf++)
        #pragma unroll
        for (int r = 0; r < 4; r++) oacc[nf][r] = 0.0f;
    float m0 = -1e30f, m1 = -1e30f, l0 = 0.0f, l1 = 0.0f;

    const int ntiles = qb + 1;

    for (int tix = 0; tix < ntiles; tix++) {
        const int kv0 = tix << 6;

        __syncthreads();   // all warps done reading prev Ks/Vs
        #pragma unroll
        for (int i = 0; i < 8; i++) {
            int idx = i * 128 + tid;         // 1024 float4 slots
            int r = idx >> 4, c4 = idx & 15;
            float4 kf = *(const float4*)(Kb + (size_t)(kv0 + r) * KD + c4 * 4);
            float4 vf = *(const float4*)(Vb + (size_t)(kv0 + r) * KD + c4 * 4);
            *(uint4*)(Ks + r * FPAD + c4 * 4) =
                make_uint4(round_tf32(kf.x), round_tf32(kf.y),
                           round_tf32(kf.z), round_tf32(kf.w));
            *(uint4*)(Vs + r * FPAD + c4 * 4) =
                make_uint4(round_tf32(vf.x), round_tf32(vf.y),
                           round_tf32(vf.z), round_tf32(vf.w));
        }
        __syncthreads();

        // ---- S = Q K^T : sacc[nf] covers kv cols kv0+8nf..+7 ----
        float sacc[8][4];
        #pragma unroll
        for (int nf = 0; nf < 8; nf++)
            #pragma unroll
            for (int r = 0; r < 4; r++) sacc[nf][r] = 0.0f;
        #pragma unroll
        for (int kk = 0; kk < 8; kk++) {
            #pragma unroll
            for (int nf = 0; nf < 8; nf++) {
                uint32_t bk[2];
                bk[0] = __float_as_uint(Ks[(nf * 8 + g) * FPAD + kk * 8 + t]);
                bk[1] = __float_as_uint(Ks[(nf * 8 + g) * FPAD + kk * 8 + t + 4]);
                MMA_TF32(sacc[nf], qa[kk], bk);
            }
        }

        // ---- mask + alibi (log2 domain), row maxima ----
        float mx0 = -1e30f, mx1 = -1e30f;
        #pragma unroll
        for (int nf = 0; nf < 8; nf++) {
            int c0 = kv0 + nf * 8 + 2 * t;
            #pragma unroll
            for (int e = 0; e < 2; e++) {
                int col = c0 + e;
                float lv = sacc[nf][e] + slope2 * (float)(r0 - col);
                lv = (col <= r0) ? lv : -1e30f;
                sacc[nf][e] = lv;
                mx0 = fmaxf(mx0, lv);
                float lw = sacc[nf][2 + e] + slope2 * (float)(r0 + 8 - col);
                lw = (col <= r0 + 8) ? lw : -1e30f;
                sacc[nf][2 + e] = lw;
                mx1 = fmaxf(mx1, lw);
            }
        }
        mx0 = fmaxf(mx0, __shfl_xor_sync(0xffffffffu, mx0, 1));
        mx0 = fmaxf(mx0, __shfl_xor_sync(0xffffffffu, mx0, 2));
        mx1 = fmaxf(mx1, __shfl_xor_sync(0xffffffffu, mx1, 1));
        mx1 = fmaxf(mx1, __shfl_xor_sync(0xffffffffu, mx1, 2));

        const float mn0 = fmaxf(m0, mx0), mn1 = fmaxf(m1, mx1);
        const float cr0 = exp2f(m0 - mn0), cr1 = exp2f(m1 - mn1);
        m0 = mn0; m1 = mn1;

        // ---- p = exp2(s - m); keep tf32-rounded P in sacc regs; row sums ----
        float s0 = 0.0f, s1 = 0.0f;
        #pragma unroll
        for (int nf = 0; nf < 8; nf++) {
            float p0 = exp2f(sacc[nf][0] - mn0);
            float p1 = exp2f(sacc[nf][1] - mn0);
            float p2 = exp2f(sacc[nf][2] - mn1);
            float p3 = exp2f(sacc[nf][3] - mn1);
            s0 += p0 + p1;
            s1 += p2 + p3;
            sacc[nf][0] = __uint_as_float(round_tf32(p0));
            sacc[nf][1] = __uint_as_float(round_tf32(p1));
            sacc[nf][2] = __uint_as_float(round_tf32(p2));
            sacc[nf][3] = __uint_as_float(round_tf32(p3));
        }
        s0 += __shfl_xor_sync(0xffffffffu, s0, 1);
        s0 += __shfl_xor_sync(0xffffffffu, s0, 2);
        s1 += __shfl_xor_sync(0xffffffffu, s1, 1);
        s1 += __shfl_xor_sync(0xffffffffu, s1, 2);
        l0 = l0 * cr0 + s0;
        l1 = l1 * cr1 + s1;

        #pragma unroll
        for (int nf = 0; nf < 8; nf++) {
            oacc[nf][0] *= cr0; oacc[nf][1] *= cr0;
            oacc[nf][2] *= cr1; oacc[nf][3] *= cr1;
        }

        // ---- O += P V  (P acc-frag -> A-frag via intra-quad shfl) ----
        const int srcA = (lane & ~3) | (t >> 1);
        const int srcB = srcA + 2;
        const bool odd = (t & 1);
        #pragma unroll
        for (int kk = 0; kk < 8; kk++) {
            float x0 = __shfl_sync(0xffffffffu, sacc[kk][0], srcA);
            float x1 = __shfl_sync(0xffffffffu, sacc[kk][1], srcA);
            float x2 = __shfl_sync(0xffffffffu, sacc[kk][2], srcA);
            float x3 = __shfl_sync(0xffffffffu, sacc[kk][3], srcA);
            float y0 = __shfl_sync(0xffffffffu, sacc[kk][0], srcB);
            float y1 = __shfl_sync(0xffffffffu, sacc[kk][1], srcB);
            float y2 = __shfl_sync(0xffffffffu, sacc[kk][2], srcB);
            float y3 = __shfl_sync(0xffffffffu, sacc[kk][3], srcB);
            uint32_t pa[4];
            pa[0] = __float_as_uint(odd ? x1 : x0);   // (row g,   col t)
            pa[1] = __float_as_uint(odd ? x3 : x2);   // (row g+8, col t)
            pa[2] = __float_as_uint(odd ? y1 : y0);   // (row g,   col t+4)
            pa[3] = __float_as_uint(odd ? y3 : y2);   // (row g+8, col t+4)
            #pragma unroll
            for (int nf = 0; nf < 8; nf++) {
                uint32_t bv[2];
                bv[0] = __float_as_uint(Vs[(kk * 8 + t) * FPAD + nf * 8 + g]);
                bv[1] = __float_as_uint(Vs[(kk * 8 + t + 4) * FPAD + nf * 8 + g]);
                MMA_TF32(oacc[nf], pa, bv);
            }
        }
    }

    // ---- epilogue: O row-major [B*S][H*Kd] ----
    const float i0 = 1.0f / l0, i1 = 1.0f / l1;
    #pragma unroll
    for (int nf = 0; nf < 8; nf++) {
        int col = h * KD + nf * 8 + 2 * t;
        *(float2*)(O + (size_t)(b * S_LEN + r0) * P_DIM + col) =
            make_float2(oacc[nf][0] * i0, oacc[nf][1] * i0);
        *(float2*)(O + (size_t)(b * S_LEN + r0 + 8) * P_DIM + col) =
            make_float2(oacc[nf][2] * i1, oacc[nf][3] * i1);
    }
}

// ---------------------------------------------------------------------------
extern "C" void kernel_launch(void* const* d_in, const int* in_sizes, int n_in,
                              void* d_out, int out_size)
{
    const float* query = (const float*)d_in[0];
    const float* key   = (const float*)d_in[1];
    const float* value = (const float*)d_in[2];
    const float* Wq    = (const float*)d_in[3];
    const float* bq    = (const float*)d_in[4];
    const float* Wk    = (const float*)d_in[5];
    const float* bk    = (const float*)d_in[6];
    const float* Wv    = (const float*)d_in[7];
    const float* bv    = (const float*)d_in[8];
    const float* Wo    = (const float*)d_in[9];
    const float* bo    = (const float*)d_in[10];
    float* out = (float*)d_out;

    float *qbuf, *kbuf, *vbuf, *abuf, *wt;
    cudaGetSymbolAddress((void**)&qbuf, g_q);
    cudaGetSymbolAddress((void**)&kbuf, g_k);
    cudaGetSymbolAddress((void**)&vbuf, g_v);
    cudaGetSymbolAddress((void**)&abuf, g_attn);
    cudaGetSymbolAddress((void**)&wt, g_wt);
    float* wtq = wt;
    float* wtk = wt + (size_t)D_MODEL * P_DIM;
    float* wtv = wt + 2 * (size_t)D_MODEL * P_DIM;
    float* wto = wt + 3 * (size_t)D_MODEL * P_DIM;

    dim3 tb(32, 8), tg(32, 32);
    transpose_round<<<tg, tb>>>(Wq, wtq);
    transpose_round<<<tg, tb>>>(Wk, wtk);
    transpose_round<<<tg, tb>>>(Wv, wtv);
    transpose_round<<<tg, tb>>>(Wo, wto);

    dim3 gemmGrid(P_DIM / 128, M_ROWS / 128);   // (8, 64)
    gemm_tf32<1><<<gemmGrid, 128>>>(query, wtq, bq, qbuf);
    gemm_tf32<1><<<gemmGrid, 128>>>(key,   wtk, bk, kbuf);
    gemm_tf32<1><<<gemmGrid, 128>>>(value, wtv, bv, vbuf);

    dim3 attnGrid(S_LEN / 64, BATCH * NHEADS);  // (32, 64): x=qb, y=bh
    flash_alibi_tc<<<attnGrid, 128, FA_SMEM>>>(qbuf, kbuf, vbuf, abuf);

    gemm_tf32<0><<<gemmGrid, 128>>>(abuf, wto, bo, out);
}

// round 9
// speedup vs baseline: 1.4588x; 1.4588x over previous
#include <cuda_runtime.h>
#include <cuda_fp16.h>
#include <math.h>
#include <stdint.h>

#define BATCH   4
#define S_LEN   2048
#define D_MODEL 1024
#define NHEADS  16
#define KD      64
#define M_ROWS  (BATCH * S_LEN)   // 8192
#define P_DIM   (NHEADS * KD)     // 1024

// ---------------------------------------------------------------------------
// Scratch (allocation-free rule: static __device__ globals)
// ---------------------------------------------------------------------------
__device__ float g_q[(size_t)M_ROWS * P_DIM];      // [B,H,S,Kd]
__device__ float g_k[(size_t)M_ROWS * P_DIM];      // [B,H,S,Kd]
__device__ float g_v[(size_t)M_ROWS * P_DIM];      // [B,H,S,Kd]
__device__ float g_attn[(size_t)M_ROWS * P_DIM];   // [B*S, H*Kd]
__device__ __half g_wt[4][(size_t)D_MODEL * P_DIM]; // transposed fp16 weights

// ---------------------------------------------------------------------------
// Base-ISA helpers (sm_103 WITHOUT 'a' — no tcgen05 anywhere)
// ---------------------------------------------------------------------------
__device__ __forceinline__ uint32_t round_tf32(float x) {
    uint32_t r;
    asm("cvt.rna.tf32.f32 %0, %1;" : "=r"(r) : "f"(x));
    return r;
}
__device__ __forceinline__ uint32_t f2h2(float x, float y) {
    __half2 h = __floats2half2_rn(x, y);
    return *(uint32_t*)&h;
}

// mma.sync m16n8k8 tf32 (attention)
#define MMA_TF32(d, a, b)                                                     \
    asm volatile(                                                             \
        "mma.sync.aligned.m16n8k8.row.col.f32.tf32.tf32.f32 "                 \
        "{%0,%1,%2,%3}, {%4,%5,%6,%7}, {%8,%9}, {%0,%1,%2,%3};"               \
        : "+f"((d)[0]), "+f"((d)[1]), "+f"((d)[2]), "+f"((d)[3])              \
        : "r"((a)[0]), "r"((a)[1]), "r"((a)[2]), "r"((a)[3]),                 \
          "r"((b)[0]), "r"((b)[1]))

// mma.sync m16n8k16 fp16 (GEMMs)
#define MMA_F16(d, a, b)                                                      \
    asm volatile(                                                             \
        "mma.sync.aligned.m16n8k16.row.col.f32.f16.f16.f32 "                  \
        "{%0,%1,%2,%3}, {%4,%5,%6,%7}, {%8,%9}, {%0,%1,%2,%3};"               \
        : "+f"((d)[0]), "+f"((d)[1]), "+f"((d)[2]), "+f"((d)[3])              \
        : "r"((a)[0]), "r"((a)[1]), "r"((a)[2]), "r"((a)[3]),                 \
          "r"((b)[0]), "r"((b)[1]))

// ---------------------------------------------------------------------------
// Weight transpose + fp16 convert: WT[n][k] = half(W[k][n]), 1024x1024
// ---------------------------------------------------------------------------
__global__ __launch_bounds__(256)
void transpose_half(const float* __restrict__ W, __half* __restrict__ WT)
{
    __shared__ float t[32][33];
    const int bx = blockIdx.x * 32, by = blockIdx.y * 32;
    const int x = threadIdx.x, y = threadIdx.y;
    #pragma unroll
    for (int i = 0; i < 32; i += 8)
        t[y + i][x] = W[(size_t)(by + y + i) * 1024 + bx + x];
    __syncthreads();
    #pragma unroll
    for (int i = 0; i < 32; i += 8)
        WT[(size_t)(bx + y + i) * 1024 + by + x] = __float2half_rn(t[x][y + i]);
}

// ---------------------------------------------------------------------------
// HMMA fp16 GEMM: C = A[8192,1024] * BT^T + bias  (BT = B^T as fp16 [N][K]).
// CTA 128x128, 128 threads, warp tile 64x64, BK=32 (2 x k16 per stage),
// double-buffered fragment-major smem, XOR swizzle sw = ks + 2*kh.
//
// smem per buffer (uint32 words):
//   A: [mf 8][ks 2][reg 4][lane 32]  = 2048 words (reg = 2*kh + rowhalf)
//   B: [nf 16][ks 2][reg 2][lane 32] = 2048 words (reg = kh)
// phys lane = logical lane ^ (4*sw).
// OUT_MODE 0: row-major [M,1024]; OUT_MODE 1: [B,H,S,Kd] scatter.
// ---------------------------------------------------------------------------
#define GBK 32
#define GNS (D_MODEL / GBK)   // 32 stages

template <int OUT_MODE>
__global__ __launch_bounds__(128)
void gemm_f16(const float* __restrict__ A, const __half* __restrict__ BT,
              const float* __restrict__ bias, float* __restrict__ C)
{
    __shared__ uint32_t sm[2 * 4096];   // 32 KB

    const int tid  = threadIdx.x;
    const int lane = tid & 31;
    const int wid  = tid >> 5;
    const int wmf  = (wid >> 1) * 4;    // warp mf base: 0 / 4
    const int wnf  = (wid & 1) * 8;     // warp nf base: 0 / 8
    const int rowBase = blockIdx.y * 128;
    const int colBase = blockIdx.x * 128;

    float acc[4][8][4];
    #pragma unroll
    for (int mf = 0; mf < 4; mf++)
        #pragma unroll
        for (int nf = 0; nf < 8; nf++)
            #pragma unroll
            for (int r = 0; r < 4; r++) acc[mf][nf][r] = 0.0f;

    uint2 stA[8];   // 8 x (4 floats -> 2 half2)
    uint4 stB[4];   // 4 x (8 halves)

    // ---- prologue: LDG stage 0 ----
    #pragma unroll
    for (int j = 0; j < 8; j++) {
        int idx = j * 128 + tid;
        int row = idx >> 3, c = idx & 7;
        float4 va = *(const float4*)(A + (size_t)(rowBase + row) * D_MODEL + 4 * c);
        stA[j] = make_uint2(f2h2(va.x, va.y), f2h2(va.z, va.w));
    }
    #pragma unroll
    for (int j = 0; j < 4; j++) {
        int idx = j * 128 + tid;
        int n = idx >> 2, cp = idx & 3;
        stB[j] = *(const uint4*)(BT + (size_t)(colBase + n) * D_MODEL + 8 * cp);
    }

    for (int s = 0; s < GNS; s++) {
        uint32_t* base = sm + (s & 1) * 4096;

        // ---- STS stage s (fragment-major, swizzled) ----
        #pragma unroll
        for (int j = 0; j < 8; j++) {
            int idx = j * 128 + tid;
            int row = idx >> 3, c = idx & 7;
            int ks = c >> 2, kh = (c >> 1) & 1, tt = 2 * (c & 1);
            int sw = ks + 2 * kh;
            int mf = row >> 4, rh = (row >> 3) & 1, r8 = row & 7;
            int blk = (mf * 2 + ks) * 4 + (kh * 2 + rh);
            *(uint2*)(base + blk * 32 + ((4 * r8) ^ (4 * sw)) + tt) = stA[j];
        }
        #pragma unroll
        for (int j = 0; j < 4; j++) {
            int idx = j * 128 + tid;
            int n = idx >> 2, cp = idx & 3;
            int ks = cp >> 1, kh = cp & 1;
            int sw = ks + 2 * kh;
            int nf = n >> 3, n8 = n & 7;
            int blk = (nf * 2 + ks) * 2 + kh;
            *(uint4*)(base + 2048 + blk * 32 + ((4 * n8) ^ (4 * sw))) = stB[j];
        }
        __syncthreads();

        // ---- LDG stage s+1 ----
        if (s + 1 < GNS) {
            int k0 = (s + 1) * GBK;
            #pragma unroll
            for (int j = 0; j < 8; j++) {
                int idx = j * 128 + tid;
                int row = idx >> 3, c = idx & 7;
                float4 va = *(const float4*)(A + (size_t)(rowBase + row) * D_MODEL +
                                             k0 + 4 * c);
                stA[j] = make_uint2(f2h2(va.x, va.y), f2h2(va.z, va.w));
            }
            #pragma unroll
            for (int j = 0; j < 4; j++) {
                int idx = j * 128 + tid;
                int n = idx >> 2, cp = idx & 3;
                stB[j] = *(const uint4*)(BT + (size_t)(colBase + n) * D_MODEL +
                                         k0 + 8 * cp);
            }
        }

        // ---- compute: 2 x k16 steps ----
        #pragma unroll
        for (int ks = 0; ks < 2; ks++) {
            uint32_t a[4][4];
            uint32_t b[8][2];
            #pragma unroll
            for (int mf = 0; mf < 4; mf++) {
                int gmf = wmf + mf;
                #pragma unroll
                for (int r = 0; r < 4; r++) {
                    int sw = ks + 2 * (r >> 1);
                    a[mf][r] = base[((gmf * 2 + ks) * 4 + r) * 32 +
                                    (lane ^ (4 * sw))];
                }
            }
            #pragma unroll
            for (int nf = 0; nf < 8; nf++) {
                int gnf = wnf + nf;
                #pragma unroll
                for (int r = 0; r < 2; r++) {
                    int sw = ks + 2 * r;
                    b[nf][r] = base[2048 + ((gnf * 2 + ks) * 2 + r) * 32 +
                                    (lane ^ (4 * sw))];
                }
            }
            #pragma unroll
            for (int mf = 0; mf < 4; mf++)
                #pragma unroll
                for (int nf = 0; nf < 8; nf++)
                    MMA_F16(acc[mf][nf], a[mf], b[nf]);
        }
        __syncthreads();
    }

    // ---- epilogue (same fragment map as tf32, validated R6/R7) ----
    #pragma unroll
    for (int nf = 0; nf < 8; nf++) {
        int col = colBase + (wnf + nf) * 8 + 2 * (lane & 3);
        float b0 = bias[col], b1 = bias[col + 1];
        #pragma unroll
        for (int mf = 0; mf < 4; mf++) {
            int row0 = rowBase + (wmf + mf) * 16 + (lane >> 2);
            #pragma unroll
            for (int half = 0; half < 2; half++) {
                int row = row0 + half * 8;
                float v0 = acc[mf][nf][2 * half]     + b0;
                float v1 = acc[mf][nf][2 * half + 1] + b1;
                float* dst;
                if (OUT_MODE == 0) {
                    dst = C + (size_t)row * D_MODEL + col;
                } else {
                    int bb = row >> 11, srow = row & 2047;
                    int h = col >> 6, d0 = col & 63;
                    dst = C + (((size_t)(bb * NHEADS + h) * S_LEN + srow) * KD + d0);
                }
                *(float2*)dst = make_float2(v0, v1);
            }
        }
    }
}

// ---------------------------------------------------------------------------
// Tensor-core flash attention (tf32 HMMA), causal + ALiBi — R7 version
// restored verbatim (known-good 1028us class).
// ---------------------------------------------------------------------------
#define FPAD 72
#define FA_SMEM (3 * 64 * FPAD * 4)   // Ks + Vs + Ps = 55296 bytes

__global__ __launch_bounds__(128)
void flash_alibi_tc(const float* __restrict__ Q, const float* __restrict__ K,
                    const float* __restrict__ V, float* __restrict__ O)
{
    extern __shared__ float fsm[];
    float* Ks = fsm;                    // [64][FPAD] tf32 bits
    float* Vs = fsm + 64 * FPAD;        // [64][FPAD] tf32 bits
    float* Ps = fsm + 2 * 64 * FPAD;    // [4][16][FPAD] tf32 bits

    const int bh = blockIdx.x;
    const int h  = bh & (NHEADS - 1);
    const int b  = bh >> 4;
    const int qb = (int)gridDim.y - 1 - (int)blockIdx.y;  // heavy blocks first
    const int q0 = qb << 6;
    const int tid = threadIdx.x;
    const int lane = tid & 31;
    const int wid  = tid >> 5;
    const int g = lane >> 2;
    const int t = lane & 3;

    const float slope = exp2f(-0.5f * (float)(h + 1));
    const int r0 = q0 + wid * 16 + g;
    const float* Qb = Q + (size_t)bh * S_LEN * KD;
    const float* Kb = K + (size_t)bh * S_LEN * KD;
    const float* Vb = V + (size_t)bh * S_LEN * KD;

    uint32_t qa[8][4];
    #pragma unroll
    for (int kk = 0; kk < 8; kk++) {
        int d = kk * 8 + t;
        qa[kk][0] = round_tf32(Qb[(size_t)r0 * KD + d] * 0.125f);
        qa[kk][1] = round_tf32(Qb[(size_t)(r0 + 8) * KD + d] * 0.125f);
        qa[kk][2] = round_tf32(Qb[(size_t)r0 * KD + d + 4] * 0.125f);
        qa[kk][3] = round_tf32(Qb[(size_t)(r0 + 8) * KD + d + 4] * 0.125f);
    }

    float oacc[8][4];
    #pragma unroll
    for (int nf = 0; nf < 8; nf++)
        #pragma unroll
        for (int r = 0; r < 4; r++) oacc[nf][r] = 0.0f;
    float m0 = -1e30f, m1 = -1e30f, l0 = 0.0f, l1 = 0.0f;

    float* Pw = Ps + wid * 16 * FPAD;
    const int ntiles = qb + 1;

    for (int tix = 0; tix < ntiles; tix++) {
        const int kv0 = tix << 6;

        __syncthreads();
        #pragma unroll
        for (int i = 0; i < 8; i++) {
            int idx = i * 128 + tid;
            int r = idx >> 4, c4 = idx & 15;
            float4 kf = *(const float4*)(Kb + (size_t)(kv0 + r) * KD + c4 * 4);
            float4 vf = *(const float4*)(Vb + (size_t)(kv0 + r) * KD + c4 * 4);
            *(uint4*)(Ks + r * FPAD + c4 * 4) =
                make_uint4(round_tf32(kf.x), round_tf32(kf.y),
                           round_tf32(kf.z), round_tf32(kf.w));
            *(uint4*)(Vs + r * FPAD + c4 * 4) =
                make_uint4(round_tf32(vf.x), round_tf32(vf.y),
                           round_tf32(vf.z), round_tf32(vf.w));
        }
        __syncthreads();

        float sacc[8][4];
        #pragma unroll
        for (int nf = 0; nf < 8; nf++)
            #pragma unroll
            for (int r = 0; r < 4; r++) sacc[nf][r] = 0.0f;
        #pragma unroll
        for (int kk = 0; kk < 8; kk++) {
            #pragma unroll
            for (int nf = 0; nf < 8; nf++) {
                uint32_t bk[2];
                bk[0] = __float_as_uint(Ks[(nf * 8 + g) * FPAD + kk * 8 + t]);
                bk[1] = __float_as_uint(Ks[(nf * 8 + g) * FPAD + kk * 8 + t + 4]);
                MMA_TF32(sacc[nf], qa[kk], bk);
            }
        }

        float mx0 = -1e30f, mx1 = -1e30f;
        #pragma unroll
        for (int nf = 0; nf < 8; nf++) {
            int c0 = kv0 + nf * 8 + 2 * t;
            #pragma unroll
            for (int e = 0; e < 2; e++) {
                int col = c0 + e;
                float lv = sacc[nf][e] + slope * (float)(r0 - col);
                lv = (col <= r0) ? lv : -1e30f;
                sacc[nf][e] = lv;
                mx0 = fmaxf(mx0, lv);
                float lw = sacc[nf][2 + e] + slope * (float)(r0 + 8 - col);
                lw = (col <= r0 + 8) ? lw : -1e30f;
                sacc[nf][2 + e] = lw;
                mx1 = fmaxf(mx1, lw);
            }
        }
        mx0 = fmaxf(mx0, __shfl_xor_sync(0xffffffffu, mx0, 1));
        mx0 = fmaxf(mx0, __shfl_xor_sync(0xffffffffu, mx0, 2));
        mx1 = fmaxf(mx1, __shfl_xor_sync(0xffffffffu, mx1, 1));
        mx1 = fmaxf(mx1, __shfl_xor_sync(0xffffffffu, mx1, 2));

        const float mn0 = fmaxf(m0, mx0), mn1 = fmaxf(m1, mx1);
        const float cr0 = __expf(m0 - mn0), cr1 = __expf(m1 - mn1);
        m0 = mn0; m1 = mn1;

        float s0 = 0.0f, s1 = 0.0f;
        #pragma unroll
        for (int nf = 0; nf < 8; nf++) {
            float p0 = __expf(sacc[nf][0] - mn0);
            float p1 = __expf(sacc[nf][1] - mn0);
            float p2 = __expf(sacc[nf][2] - mn1);
            float p3 = __expf(sacc[nf][3] - mn1);
            s0 += p0 + p1;
            s1 += p2 + p3;
            int c = nf * 8 + 2 * t;
            Pw[g * FPAD + c]           = __uint_as_float(round_tf32(p0));
            Pw[g * FPAD + c + 1]       = __uint_as_float(round_tf32(p1));
            Pw[(g + 8) * FPAD + c]     = __uint_as_float(round_tf32(p2));
            Pw[(g + 8) * FPAD + c + 1] = __uint_as_float(round_tf32(p3));
        }
        s0 += __shfl_xor_sync(0xffffffffu, s0, 1);
        s0 += __shfl_xor_sync(0xffffffffu, s0, 2);
        s1 += __shfl_xor_sync(0xffffffffu, s1, 1);
        s1 += __shfl_xor_sync(0xffffffffu, s1, 2);
        l0 = l0 * cr0 + s0;
        l1 = l1 * cr1 + s1;

        #pragma unroll
        for (int nf = 0; nf < 8; nf++) {
            oacc[nf][0] *= cr0; oacc[nf][1] *= cr0;
            oacc[nf][2] *= cr1; oacc[nf][3] *= cr1;
        }
        __syncwarp();

        #pragma unroll
        for (int kk = 0; kk < 8; kk++) {
            uint32_t pa[4];
            pa[0] = __float_as_uint(Pw[g * FPAD + kk * 8 + t]);
            pa[1] = __float_as_uint(Pw[(g + 8) * FPAD + kk * 8 + t]);
            pa[2] = __float_as_uint(Pw[g * FPAD + kk * 8 + t + 4]);
            pa[3] = __float_as_uint(Pw[(g + 8) * FPAD + kk * 8 + t + 4]);
            #pragma unroll
            for (int nf = 0; nf < 8; nf++) {
                uint32_t bv[2];
                bv[0] = __float_as_uint(Vs[(kk * 8 + t) * FPAD + nf * 8 + g]);
                bv[1] = __float_as_uint(Vs[(kk * 8 + t + 4) * FPAD + nf * 8 + g]);
                MMA_TF32(oacc[nf], pa, bv);
            }
        }
        __syncwarp();
    }

    const float i0 = 1.0f / l0, i1 = 1.0f / l1;
    #pragma unroll
    for (int nf = 0; nf < 8; nf++) {
        int col = h * KD + nf * 8 + 2 * t;
        *(float2*)(O + (size_t)(b * S_LEN + r0) * P_DIM + col) =
            make_float2(oacc[nf][0] * i0, oacc[nf][1] * i0);
        *(float2*)(O + (size_t)(b * S_LEN + r0 + 8) * P_DIM + col) =
            make_float2(oacc[nf][2] * i1, oacc[nf][3] * i1);
    }
}

// ---------------------------------------------------------------------------
extern "C" void kernel_launch(void* const* d_in, const int* in_sizes, int n_in,
                              void* d_out, int out_size)
{
    const float* query = (const float*)d_in[0];
    const float* key   = (const float*)d_in[1];
    const float* value = (const float*)d_in[2];
    const float* Wq    = (const float*)d_in[3];
    const float* bq    = (const float*)d_in[4];
    const float* Wk    = (const float*)d_in[5];
    const float* bk    = (const float*)d_in[6];
    const float* Wv    = (const float*)d_in[7];
    const float* bv    = (const float*)d_in[8];
    const float* Wo    = (const float*)d_in[9];
    const float* bo    = (const float*)d_in[10];
    float* out = (float*)d_out;

    float *qbuf, *kbuf, *vbuf, *abuf;
    __half* wt;
    cudaGetSymbolAddress((void**)&qbuf, g_q);
    cudaGetSymbolAddress((void**)&kbuf, g_k);
    cudaGetSymbolAddress((void**)&vbuf, g_v);
    cudaGetSymbolAddress((void**)&abuf, g_attn);
    cudaGetSymbolAddress((void**)&wt, g_wt);
    __half* wtq = wt;
    __half* wtk = wt + (size_t)D_MODEL * P_DIM;
    __half* wtv = wt + 2 * (size_t)D_MODEL * P_DIM;
    __half* wto = wt + 3 * (size_t)D_MODEL * P_DIM;

    cudaFuncSetAttribute(flash_alibi_tc,
        cudaFuncAttributeMaxDynamicSharedMemorySize, FA_SMEM);

    dim3 tb(32, 8), tg(32, 32);
    transpose_half<<<tg, tb>>>(Wq, wtq);
    transpose_half<<<tg, tb>>>(Wk, wtk);
    transpose_half<<<tg, tb>>>(Wv, wtv);
    transpose_half<<<tg, tb>>>(Wo, wto);

    dim3 gemmGrid(P_DIM / 128, M_ROWS / 128);   // (8, 64)
    gemm_f16<1><<<gemmGrid, 128>>>(query, wtq, bq, qbuf);
    gemm_f16<1><<<gemmGrid, 128>>>(key,   wtk, bk, kbuf);
    gemm_f16<1><<<gemmGrid, 128>>>(value, wtv, bv, vbuf);

    dim3 attnGrid(BATCH * NHEADS, S_LEN / 64);  // (64, 32)
    flash_alibi_tc<<<attnGrid, 128, FA_SMEM>>>(qbuf, kbuf, vbuf, abuf);

    gemm_f16<0><<<gemmGrid, 128>>>(abuf, wto, bo, out);
}

// round 14
// speedup vs baseline: 1.7497x; 1.1994x over previous
#include <cuda_runtime.h>
#include <cuda_fp16.h>
#include <math.h>
#include <stdint.h>

#define BATCH   4
#define S_LEN   2048
#define D_MODEL 1024
#define NHEADS  16
#define KD      64
#define M_ROWS  (BATCH * S_LEN)   // 8192
#define P_DIM   (NHEADS * KD)     // 1024

// ---------------------------------------------------------------------------
// Scratch (allocation-free rule: static __device__ globals)
// ---------------------------------------------------------------------------
__device__ float g_q[(size_t)M_ROWS * P_DIM];      // [B,H,S,Kd]
__device__ float g_k[(size_t)M_ROWS * P_DIM];      // [B,H,S,Kd]
__device__ float g_v[(size_t)M_ROWS * P_DIM];      // [B,H,S,Kd]
__device__ float g_attn[(size_t)M_ROWS * P_DIM];   // [B*S, H*Kd]
__device__ __half g_wt[4][(size_t)D_MODEL * P_DIM]; // transposed fp16 weights

// ---------------------------------------------------------------------------
// Helpers
// ---------------------------------------------------------------------------
__device__ __forceinline__ uint32_t f2h2(float x, float y) {
    __half2 h = __floats2half2_rn(x, y);
    return *(uint32_t*)&h;
}

// mma.sync m16n8k16 fp16
#define MMA_F16(d, a, b)                                                      \
    asm volatile(                                                             \
        "mma.sync.aligned.m16n8k16.row.col.f32.f16.f16.f32 "                  \
        "{%0,%1,%2,%3}, {%4,%5,%6,%7}, {%8,%9}, {%0,%1,%2,%3};"               \
        : "+f"((d)[0]), "+f"((d)[1]), "+f"((d)[2]), "+f"((d)[3])              \
        : "r"((a)[0]), "r"((a)[1]), "r"((a)[2]), "r"((a)[3]),                 \
          "r"((b)[0]), "r"((b)[1]))

// ---------------------------------------------------------------------------
// Weight transpose + fp16 convert: WT[n][k] = half(W[k][n]), 1024x1024
// ---------------------------------------------------------------------------
__global__ __launch_bounds__(256)
void transpose_half(const float* __restrict__ W, __half* __restrict__ WT)
{
    __shared__ float t[32][33];
    const int bx = blockIdx.x * 32, by = blockIdx.y * 32;
    const int x = threadIdx.x, y = threadIdx.y;
    #pragma unroll
    for (int i = 0; i < 32; i += 8)
        t[y + i][x] = W[(size_t)(by + y + i) * 1024 + bx + x];
    __syncthreads();
    #pragma unroll
    for (int i = 0; i < 32; i += 8)
        WT[(size_t)(bx + y + i) * 1024 + by + x] = __float2half_rn(t[x][y + i]);
}

// ---------------------------------------------------------------------------
// HMMA fp16 GEMM (validated R9): C = A[8192,1024] * BT^T + bias.
// ---------------------------------------------------------------------------
#define GBK 32
#define GNS (D_MODEL / GBK)   // 32 stages

template <int OUT_MODE>
__global__ __launch_bounds__(128)
void gemm_f16(const float* __restrict__ A, const __half* __restrict__ BT,
              const float* __restrict__ bias, float* __restrict__ C)
{
    __shared__ uint32_t sm[2 * 4096];   // 32 KB

    const int tid  = threadIdx.x;
    const int lane = tid & 31;
    const int wid  = tid >> 5;
    const int wmf  = (wid >> 1) * 4;
    const int wnf  = (wid & 1) * 8;
    const int rowBase = blockIdx.y * 128;
    const int colBase = blockIdx.x * 128;

    float acc[4][8][4];
    #pragma unroll
    for (int mf = 0; mf < 4; mf++)
        #pragma unroll
        for (int nf = 0; nf < 8; nf++)
            #pragma unroll
            for (int r = 0; r < 4; r++) acc[mf][nf][r] = 0.0f;

    uint2 stA[8];
    uint4 stB[4];

    #pragma unroll
    for (int j = 0; j < 8; j++) {
        int idx = j * 128 + tid;
        int row = idx >> 3, c = idx & 7;
        float4 va = *(const float4*)(A + (size_t)(rowBase + row) * D_MODEL + 4 * c);
        stA[j] = make_uint2(f2h2(va.x, va.y), f2h2(va.z, va.w));
    }
    #pragma unroll
    for (int j = 0; j < 4; j++) {
        int idx = j * 128 + tid;
        int n = idx >> 2, cp = idx & 3;
        stB[j] = *(const uint4*)(BT + (size_t)(colBase + n) * D_MODEL + 8 * cp);
    }

    for (int s = 0; s < GNS; s++) {
        uint32_t* base = sm + (s & 1) * 4096;

        #pragma unroll
        for (int j = 0; j < 8; j++) {
            int idx = j * 128 + tid;
            int row = idx >> 3, c = idx & 7;
            int ks = c >> 2, kh = (c >> 1) & 1, tt = 2 * (c & 1);
            int sw = ks + 2 * kh;
            int mf = row >> 4, rh = (row >> 3) & 1, r8 = row & 7;
            int blk = (mf * 2 + ks) * 4 + (kh * 2 + rh);
            *(uint2*)(base + blk * 32 + ((4 * r8) ^ (4 * sw)) + tt) = stA[j];
        }
        #pragma unroll
        for (int j = 0; j < 4; j++) {
            int idx = j * 128 + tid;
            int n = idx >> 2, cp = idx & 3;
            int ks = cp >> 1, kh = cp & 1;
            int sw = ks + 2 * kh;
            int nf = n >> 3, n8 = n & 7;
            int blk = (nf * 2 + ks) * 2 + kh;
            *(uint4*)(base + 2048 + blk * 32 + ((4 * n8) ^ (4 * sw))) = stB[j];
        }
        __syncthreads();

        if (s + 1 < GNS) {
            int k0 = (s + 1) * GBK;
            #pragma unroll
            for (int j = 0; j < 8; j++) {
                int idx = j * 128 + tid;
                int row = idx >> 3, c = idx & 7;
                float4 va = *(const float4*)(A + (size_t)(rowBase + row) * D_MODEL +
                                             k0 + 4 * c);
                stA[j] = make_uint2(f2h2(va.x, va.y), f2h2(va.z, va.w));
            }
            #pragma unroll
            for (int j = 0; j < 4; j++) {
                int idx = j * 128 + tid;
                int n = idx >> 2, cp = idx & 3;
                stB[j] = *(const uint4*)(BT + (size_t)(colBase + n) * D_MODEL +
                                         k0 + 8 * cp);
            }
        }

        #pragma unroll
        for (int ks = 0; ks < 2; ks++) {
            uint32_t a[4][4];
            uint32_t b[8][2];
            #pragma unroll
            for (int mf = 0; mf < 4; mf++) {
                int gmf = wmf + mf;
                #pragma unroll
                for (int r = 0; r < 4; r++) {
                    int sw = ks + 2 * (r >> 1);
                    a[mf][r] = base[((gmf * 2 + ks) * 4 + r) * 32 +
                                    (lane ^ (4 * sw))];
                }
            }
            #pragma unroll
            for (int nf = 0; nf < 8; nf++) {
                int gnf = wnf + nf;
                #pragma unroll
                for (int r = 0; r < 2; r++) {
                    int sw = ks + 2 * r;
                    b[nf][r] = base[2048 + ((gnf * 2 + ks) * 2 + r) * 32 +
                                    (lane ^ (4 * sw))];
                }
            }
            #pragma unroll
            for (int mf = 0; mf < 4; mf++)
                #pragma unroll
                for (int nf = 0; nf < 8; nf++)
                    MMA_F16(acc[mf][nf], a[mf], b[nf]);
        }
        __syncthreads();
    }

    #pragma unroll
    for (int nf = 0; nf < 8; nf++) {
        int col = colBase + (wnf + nf) * 8 + 2 * (lane & 3);
        float b0 = bias[col], b1 = bias[col + 1];
        #pragma unroll
        for (int mf = 0; mf < 4; mf++) {
            int row0 = rowBase + (wmf + mf) * 16 + (lane >> 2);
            #pragma unroll
            for (int half = 0; half < 2; half++) {
                int row = row0 + half * 8;
                float v0 = acc[mf][nf][2 * half]     + b0;
                float v1 = acc[mf][nf][2 * half + 1] + b1;
                float* dst;
                if (OUT_MODE == 0) {
                    dst = C + (size_t)row * D_MODEL + col;
                } else {
                    int bb = row >> 11, srow = row & 2047;
                    int h = col >> 6, d0 = col & 63;
                    dst = C + (((size_t)(bb * NHEADS + h) * S_LEN + srow) * KD + d0);
                }
                *(float2*)dst = make_float2(v0, v1);
            }
        }
    }
}

// ---------------------------------------------------------------------------
// Tensor-core flash attention, fp16 m16n8k16, causal + ALiBi.
// Grid (B*H, S/64 reversed). 4 warps, warp w = q rows [q0+16w, q0+16w+16).
// K/V tiles 64x64 fp16 in smem [64][FPH] (FPH=72: QK b-loads conflict-free,
// PV u16 pair-gathers same-word-broadcast conflict-free).
// P: S-accumulator fragment == fp16 A-operand fragment -> register-only
// conversion (no smem, no shfl).
// ---------------------------------------------------------------------------
#define FPH 72

__global__ __launch_bounds__(128)
void flash_alibi_tc(const float* __restrict__ Q, const float* __restrict__ K,
                    const float* __restrict__ V, float* __restrict__ O)
{
    __shared__ __half Ks[64 * FPH];
    __shared__ __half Vs[64 * FPH];

    const int bh = blockIdx.x;
    const int h  = bh & (NHEADS - 1);
    const int b  = bh >> 4;
    const int qb = (int)gridDim.y - 1 - (int)blockIdx.y;  // heavy blocks first
    const int q0 = qb << 6;
    const int tid = threadIdx.x;
    const int lane = tid & 31;
    const int wid  = tid >> 5;
    const int g = lane >> 2;
    const int t = lane & 3;

    const float slope = exp2f(-0.5f * (float)(h + 1));
    const int r0 = q0 + wid * 16 + g;
    const float* Qb = Q + (size_t)bh * S_LEN * KD;
    const float* Kb = K + (size_t)bh * S_LEN * KD;
    const float* Vb = V + (size_t)bh * S_LEN * KD;

    // ---- Q fragments fp16 (4 k-blocks of 16), scaled by 0.125 ----
    uint32_t qa[4][4];
    #pragma unroll
    for (int kb = 0; kb < 4; kb++) {
        int d = kb * 16 + 2 * t;
        const float* q0p = Qb + (size_t)r0 * KD + d;
        const float* q1p = Qb + (size_t)(r0 + 8) * KD + d;
        qa[kb][0] = f2h2(q0p[0] * 0.125f, q0p[1] * 0.125f);
        qa[kb][1] = f2h2(q1p[0] * 0.125f, q1p[1] * 0.125f);
        qa[kb][2] = f2h2(q0p[8] * 0.125f, q0p[9] * 0.125f);
        qa[kb][3] = f2h2(q1p[8] * 0.125f, q1p[9] * 0.125f);
    }

    float oacc[8][4];
    #pragma unroll
    for (int nf = 0; nf < 8; nf++)
        #pragma unroll
        for (int r = 0; r < 4; r++) oacc[nf][r] = 0.0f;
    float m0 = -1e30f, m1 = -1e30f, l0 = 0.0f, l1 = 0.0f;

    const int ntiles = qb + 1;

    for (int tix = 0; tix < ntiles; tix++) {
        const int kv0 = tix << 6;

        __syncthreads();
        #pragma unroll
        for (int i = 0; i < 8; i++) {
            int idx = i * 128 + tid;          // 1024 float4 slots
            int r = idx >> 4, c4 = idx & 15;
            float4 kf = *(const float4*)(Kb + (size_t)(kv0 + r) * KD + c4 * 4);
            float4 vf = *(const float4*)(Vb + (size_t)(kv0 + r) * KD + c4 * 4);
            *(uint2*)(Ks + r * FPH + c4 * 4) =
                make_uint2(f2h2(kf.x, kf.y), f2h2(kf.z, kf.w));
            *(uint2*)(Vs + r * FPH + c4 * 4) =
                make_uint2(f2h2(vf.x, vf.y), f2h2(vf.z, vf.w));
        }
        __syncthreads();

        // ---- S = Q K^T ----
        float sacc[8][4];
        #pragma unroll
        for (int nf = 0; nf < 8; nf++)
            #pragma unroll
            for (int r = 0; r < 4; r++) sacc[nf][r] = 0.0f;
        #pragma unroll
        for (int kb = 0; kb < 4; kb++) {
            #pragma unroll
            for (int nf = 0; nf < 8; nf++) {
                const __half* krow = Ks + (nf * 8 + g) * FPH + kb * 16 + 2 * t;
                uint32_t bk[2];
                bk[0] = *(const uint32_t*)krow;
                bk[1] = *(const uint32_t*)(krow + 8);
                MMA_F16(sacc[nf], qa[kb], bk);
            }
        }

        // ---- mask + alibi, row maxima ----
        float mx0 = -1e30f, mx1 = -1e30f;
        #pragma unroll
        for (int nf = 0; nf < 8; nf++) {
            int c0 = kv0 + nf * 8 + 2 * t;
            #pragma unroll
            for (int e = 0; e < 2; e++) {
                int col = c0 + e;
                float lv = sacc[nf][e] + slope * (float)(r0 - col);
                lv = (col <= r0) ? lv : -1e30f;
                sacc[nf][e] = lv;
                mx0 = fmaxf(mx0, lv);
                float lw = sacc[nf][2 + e] + slope * (float)(r0 + 8 - col);
                lw = (col <= r0 + 8) ? lw : -1e30f;
                sacc[nf][2 + e] = lw;
                mx1 = fmaxf(mx1, lw);
            }
        }
        mx0 = fmaxf(mx0, __shfl_xor_sync(0xffffffffu, mx0, 1));
        mx0 = fmaxf(mx0, __shfl_xor_sync(0xffffffffu, mx0, 2));
        mx1 = fmaxf(mx1, __shfl_xor_sync(0xffffffffu, mx1, 1));
        mx1 = fmaxf(mx1, __shfl_xor_sync(0xffffffffu, mx1, 2));

        const float mn0 = fmaxf(m0, mx0), mn1 = fmaxf(m1, mx1);
        const float cr0 = __expf(m0 - mn0), cr1 = __expf(m1 - mn1);
        m0 = mn0; m1 = mn1;

        // ---- p = exp(s - m); pack to fp16 A-fragments in registers ----
        uint32_t ph[8][2];
        float s0 = 0.0f, s1 = 0.0f;
        #pragma unroll
        for (int nf = 0; nf < 8; nf++) {
            float p0 = __expf(sacc[nf][0] - mn0);
            float p1 = __expf(sacc[nf][1] - mn0);
            float p2 = __expf(sacc[nf][2] - mn1);
            float p3 = __expf(sacc[nf][3] - mn1);
            s0 += p0 + p1;
            s1 += p2 + p3;
            ph[nf][0] = f2h2(p0, p1);   // row g,   cols 2t,2t+1
            ph[nf][1] = f2h2(p2, p3);   // row g+8, cols 2t,2t+1
        }
        s0 += __shfl_xor_sync(0xffffffffu, s0, 1);
        s0 += __shfl_xor_sync(0xffffffffu, s0, 2);
        s1 += __shfl_xor_sync(0xffffffffu, s1, 1);
        s1 += __shfl_xor_sync(0xffffffffu, s1, 2);
        l0 = l0 * cr0 + s0;
        l1 = l1 * cr1 + s1;

        #pragma unroll
        for (int nf = 0; nf < 8; nf++) {
            oacc[nf][0] *= cr0; oacc[nf][1] *= cr0;
            oacc[nf][2] *= cr1; oacc[nf][3] *= cr1;
        }

        // ---- O += P V  (P already in A-fragment layout) ----
        #pragma unroll
        for (int kb = 0; kb < 4; kb++) {
            uint32_t pa[4];
            pa[0] = ph[2 * kb][0];       // rows g,   kv 16kb+2t..+1
            pa[1] = ph[2 * kb][1];       // rows g+8
            pa[2] = ph[2 * kb + 1][0];   // rows g,   kv 16kb+8+2t..+1
            pa[3] = ph[2 * kb + 1][1];
            const uint16_t* v0 = (const uint16_t*)(Vs + (kb * 16 + 2 * t) * FPH);
            const uint16_t* v1 = v0 + FPH;
            const uint16_t* v2 = v0 + 8 * FPH;
            const uint16_t* v3 = v0 + 9 * FPH;
            #pragma unroll
            for (int nf = 0; nf < 8; nf++) {
                int col = nf * 8 + g;
                uint32_t bv[2];
                bv[0] = (uint32_t)v0[col] | ((uint32_t)v1[col] << 16);
                bv[1] = (uint32_t)v2[col] | ((uint32_t)v3[col] << 16);
                MMA_F16(oacc[nf], pa, bv);
            }
        }
    }

    // ---- epilogue: O row-major [B*S][H*Kd] ----
    const float i0 = 1.0f / l0, i1 = 1.0f / l1;
    #pragma unroll
    for (int nf = 0; nf < 8; nf++) {
        int col = h * KD + nf * 8 + 2 * t;
        *(float2*)(O + (size_t)(b * S_LEN + r0) * P_DIM + col) =
            make_float2(oacc[nf][0] * i0, oacc[nf][1] * i0);
        *(float2*)(O + (size_t)(b * S_LEN + r0 + 8) * P_DIM + col) =
            make_float2(oacc[nf][2] * i1, oacc[nf][3] * i1);
    }
}

// ---------------------------------------------------------------------------
extern "C" void kernel_launch(void* const* d_in, const int* in_sizes, int n_in,
                              void* d_out, int out_size)
{
    const float* query = (const float*)d_in[0];
    const float* key   = (const float*)d_in[1];
    const float* value = (const float*)d_in[2];
    const float* Wq    = (const float*)d_in[3];
    const float* bq    = (const float*)d_in[4];
    const float* Wk    = (const float*)d_in[5];
    const float* bk    = (const float*)d_in[6];
    const float* Wv    = (const float*)d_in[7];
    const float* bv    = (const float*)d_in[8];
    const float* Wo    = (const float*)d_in[9];
    const float* bo    = (const float*)d_in[10];
    float* out = (float*)d_out;

    float *qbuf, *kbuf, *vbuf, *abuf;
    __half* wt;
    cudaGetSymbolAddress((void**)&qbuf, g_q);
    cudaGetSymbolAddress((void**)&kbuf, g_k);
    cudaGetSymbolAddress((void**)&vbuf, g_v);
    cudaGetSymbolAddress((void**)&abuf, g_attn);
    cudaGetSymbolAddress((void**)&wt, g_wt);
    __half* wtq = wt;
    __half* wtk = wt + (size_t)D_MODEL * P_DIM;
    __half* wtv = wt + 2 * (size_t)D_MODEL * P_DIM;
    __half* wto = wt + 3 * (size_t)D_MODEL * P_DIM;

    dim3 tb(32, 8), tg(32, 32);
    transpose_half<<<tg, tb>>>(Wq, wtq);
    transpose_half<<<tg, tb>>>(Wk, wtk);
    transpose_half<<<tg, tb>>>(Wv, wtv);
    transpose_half<<<tg, tb>>>(Wo, wto);

    dim3 gemmGrid(P_DIM / 128, M_ROWS / 128);   // (8, 64)
    gemm_f16<1><<<gemmGrid, 128>>>(query, wtq, bq, qbuf);
    gemm_f16<1><<<gemmGrid, 128>>>(key,   wtk, bk, kbuf);
    gemm_f16<1><<<gemmGrid, 128>>>(value, wtv, bv, vbuf);

    dim3 attnGrid(BATCH * NHEADS, S_LEN / 64);  // (64, 32)
    flash_alibi_tc<<<attnGrid, 128>>>(qbuf, kbuf, vbuf, abuf);

    gemm_f16<0><<<gemmGrid, 128>>>(abuf, wto, bo, out);
}